// round 7
// baseline (speedup 1.0000x reference)
#include <cuda_runtime.h>
#include <cuda_fp16.h>

// Inputs (metadata order):
//  0 embed  [N,64] f32          (N=1500)
//  1 edge_index [2,E]           (E=65536; int32 OR int64, sniffed on device)
//  2 noise  [N*N] f32
//  3 tmp    [1] f32  (temperature beta)
//  4 W1     [128,64] f32
//  5 b1     [64] f32
//  6 W2     [64,1] f32
//  7 b2     [1] f32
// Output: edge_mask [E] f32

#define MAXN 1500

// Scratch: per node n, row of 128 halfs: [0:64) = h1[n]+b1, [64:128) = h2[n]
// fp16 keeps the 1500-row table at 384 KB -> mostly L1-resident per SM.
__device__ __half g_h16[MAXN * 128];
__device__ int    g_is64;   // 1 if edge_index words look like little-endian int64

// ---------------------------------------------------------------------------
// Kernel 1: h1 = embed @ W1[:64] + b1 ; h2 = embed @ W1[64:]  (stored fp16)
// 4 nodes per block, 128 threads: thread t handles 4 adjacent k of one
// node-half -> W1 accessed as float4 rows (coalesced, L1-resident).
// Block gridDim-1 does the dtype sniff instead.
// ---------------------------------------------------------------------------
__global__ void __launch_bounds__(128) precompute_h(
    const float* __restrict__ embed,
    const float* __restrict__ W1,
    const float* __restrict__ b1,
    const int*  __restrict__ eiw,   // edge_index viewed as 32-bit words
    int nwords,
    int N)
{
    int t = threadIdx.x;          // 0..127

    if (blockIdx.x == gridDim.x - 1) {
        // dtype sniff: genuine int64 (values < 2^31) -> all odd words zero.
        __shared__ int s_nz[4];
        int k = 2 * t + 1;
        int v = (k < nwords) ? eiw[k] : 0;
        unsigned nzm = __ballot_sync(0xffffffffu, v != 0);
        if ((t & 31) == 0) s_nz[t >> 5] = (nzm != 0);
        __syncthreads();
        if (t == 0)
            g_is64 = (s_nz[0] | s_nz[1] | s_nz[2] | s_nz[3]) ? 0 : 1;
        return;
    }

    __shared__ float se[4 * 64];          // 4 nodes x 64 features
    int n0 = blockIdx.x * 4;

#pragma unroll
    for (int idx = t; idx < 256; idx += 128) {
        int nl = idx >> 6, f = idx & 63;
        se[idx] = (n0 + nl < N) ? embed[(n0 + nl) * 64 + f] : 0.0f;
    }
    __syncthreads();

    int nl   = t >> 5;            // node-local 0..3 (whole warp = one node)
    int half = (t >> 4) & 1;      // 0 -> h1, 1 -> h2
    int k0   = (t & 15) * 4;      // 4 adjacent k
    int node = n0 + nl;

    const float* es = se + nl * 64;
    float4 s = make_float4(0.f, 0.f, 0.f, 0.f);
#pragma unroll
    for (int f = 0; f < 64; f++) {
        float e = es[f];
        float4 w = *(const float4*)&W1[(half * 64 + f) * 64 + k0];
        s.x = fmaf(e, w.x, s.x);
        s.y = fmaf(e, w.y, s.y);
        s.z = fmaf(e, w.z, s.z);
        s.w = fmaf(e, w.w, s.w);
    }
    if (half == 0) {
        s.x += b1[k0];  s.y += b1[k0 + 1];
        s.z += b1[k0 + 2]; s.w += b1[k0 + 3];
    }
    if (node < N) {
        __half2 lo = __floats2half2_rn(s.x, s.y);
        __half2 hi = __floats2half2_rn(s.z, s.w);
        uint2 pack;
        pack.x = *(unsigned*)&lo;
        pack.y = *(unsigned*)&hi;
        *(uint2*)&g_h16[node * 128 + half * 64 + k0] = pack;
    }
}

// ---------------------------------------------------------------------------
// Kernel 2: 4 edges per warp, no block barriers.
//   d = lane>>2 (8 directions = 4 edges x 2 dirs), m = lane&3 (16 k's each).
//   h rows fp16 (2 uint4 loads/operand), relu-add in half2, fp32 fma vs W2.
// ---------------------------------------------------------------------------
__global__ void __launch_bounds__(256) edge_gate(
    const void* __restrict__ ei_raw,
    const float* __restrict__ noise,
    const float* __restrict__ tmpp,
    const float* __restrict__ W2,
    const float* __restrict__ b2,
    float* __restrict__ out,
    int N, int E)
{
    int tid   = threadIdx.x;
    int lane  = tid & 31;
    int gwarp = (blockIdx.x * blockDim.x + tid) >> 5;

    int d   = lane >> 2;      // direction 0..7
    int m   = lane & 3;       // quarter of the 64-dot (16 k's)
    int el  = d >> 1;         // edge-local 0..3
    int top = d & 1;          // 0: (i,j), 1: (j,i)

    int e = gwarp * 4 + el;
    bool active = e < E;
    int eld = active ? e : (E > 0 ? E - 1 : 0);

    int i, j;
    if (g_is64) {
        const long long* e64 = (const long long*)ei_raw;
        i = (int)e64[eld];
        j = (int)e64[E + eld];
    } else {
        const int* e32 = (const int*)ei_raw;
        i = e32[eld];
        j = e32[E + eld];
    }
    i = min(max(i, 0), N - 1);
    j = min(max(j, 0), N - 1);

    // scattered noise load (DRAM) issued first so it overlaps the h loads
    float nz = 0.0f;
    if (m == 0) nz = __ldg(noise + (top ? (j * N + i) : (i * N + j)));

    // h1 of first node, h2 of second node for this direction (fp16 rows)
    const uint4* A4 = (const uint4*)(g_h16 + (top ? j : i) * 128);        // h1
    const uint4* B4 = (const uint4*)(g_h16 + (top ? i : j) * 128 + 64);   // h2
    const float4* W = (const float4*)W2;

    uint4 a0 = A4[2 * m], a1 = A4[2 * m + 1];   // 16 halfs = k 16m..16m+15
    uint4 c0 = B4[2 * m], c1 = B4[2 * m + 1];
    float4 w0 = W[4 * m],     w1 = W[4 * m + 1];
    float4 w2v = W[4 * m + 2], w3v = W[4 * m + 3];

    const __half2 z2 = __float2half2_rn(0.0f);
    const __half2* ah = (const __half2*)&a0;    // 4 half2 (k pairs 0..7)
    const __half2* a2h = (const __half2*)&a1;   // 4 half2 (k pairs 8..15)
    const __half2* ch = (const __half2*)&c0;
    const __half2* c2h = (const __half2*)&c1;

    float s = 0.0f;
    {
        float2 f0 = __half22float2(__hmax2(__hadd2(ah[0], ch[0]), z2));
        float2 f1 = __half22float2(__hmax2(__hadd2(ah[1], ch[1]), z2));
        float2 f2 = __half22float2(__hmax2(__hadd2(ah[2], ch[2]), z2));
        float2 f3 = __half22float2(__hmax2(__hadd2(ah[3], ch[3]), z2));
        s = fmaf(f0.x, w0.x, s); s = fmaf(f0.y, w0.y, s);
        s = fmaf(f1.x, w0.z, s); s = fmaf(f1.y, w0.w, s);
        s = fmaf(f2.x, w1.x, s); s = fmaf(f2.y, w1.y, s);
        s = fmaf(f3.x, w1.z, s); s = fmaf(f3.y, w1.w, s);
    }
    {
        float2 f0 = __half22float2(__hmax2(__hadd2(a2h[0], c2h[0]), z2));
        float2 f1 = __half22float2(__hmax2(__hadd2(a2h[1], c2h[1]), z2));
        float2 f2 = __half22float2(__hmax2(__hadd2(a2h[2], c2h[2]), z2));
        float2 f3 = __half22float2(__hmax2(__hadd2(a2h[3], c2h[3]), z2));
        s = fmaf(f0.x, w2v.x, s); s = fmaf(f0.y, w2v.y, s);
        s = fmaf(f1.x, w2v.z, s); s = fmaf(f1.y, w2v.w, s);
        s = fmaf(f2.x, w3v.x, s); s = fmaf(f2.y, w3v.y, s);
        s = fmaf(f3.x, w3v.z, s); s = fmaf(f3.y, w3v.w, s);
    }

    // reduce across the 4 lanes of this direction
    s += __shfl_xor_sync(0xffffffffu, s, 1);
    s += __shfl_xor_sync(0xffffffffu, s, 2);

    // gate on m==0 lanes (8 lanes, all 8 directions in one pass)
    float g = 0.0f;
    if (m == 0) {
        float inv_beta = 1.0f / tmpp[0];
        float x = (__logf(nz) - __logf(1.0f - nz) + s + b2[0]) * inv_beta;
        g = 1.0f / (1.0f + __expf(-x));
    }
    // combine the two directions of each edge: lane 8*el <- lane 8*el+4
    float go = __shfl_xor_sync(0xffffffffu, g, 4);
    if ((lane & 7) == 0 && active)
        out[e] = 0.5f * (g + go);
}

// ---------------------------------------------------------------------------
extern "C" void kernel_launch(void* const* d_in, const int* in_sizes, int n_in,
                              void* d_out, int out_size)
{
    const float* embed = (const float*)d_in[0];
    const void*  ei    = d_in[1];
    const float* noise = (const float*)d_in[2];
    const float* tmp   = (const float*)d_in[3];
    const float* W1    = (const float*)d_in[4];
    const float* b1    = (const float*)d_in[5];
    const float* W2    = (const float*)d_in[6];
    const float* b2    = (const float*)d_in[7];
    float*       out   = (float*)d_out;

    int N = in_sizes[0] / 64;      // 1500
    int E = in_sizes[1] / 2;       // 65536

    // ceil(N/4) compute blocks + 1 sniff block
    int pblocks = (N + 3) / 4 + 1;
    precompute_h<<<pblocks, 128>>>(embed, W1, b1, (const int*)ei,
                                   in_sizes[1] * 2, N);

    // 4 edges per warp, 8 warps per block -> 32 edges per block
    int blocks = (E + 31) / 32;
    edge_gate<<<blocks, 256>>>(ei, noise, tmp, W2, b2, out, N, E);
}